// round 2
// baseline (speedup 1.0000x reference)
#include <cuda_runtime.h>
#include <math.h>

#define BB   2
#define QQ   2048
#define KLEN 2048
#define KP   2049
#define DD   512
#define NH   8
#define HD   64
#define SCALE_F   0.125f
#define NEG_INF_F -1e30f
#define LN_EPS_F  1e-5f

// ---------------- scratch (device globals; allocation-free) ----------------
__device__ float g_QN[BB * QQ * DD];
__device__ float g_KN[BB * KP * DD];
__device__ float g_VN[BB * KP * DD];
__device__ float g_QH[BB * QQ * DD];
__device__ float g_KH[BB * KP * DD];
__device__ float g_VH[BB * KP * DD];
__device__ float g_AV[BB * QQ * DD];
__device__ float g_AVO[BB * QQ * DD];

// ---------------- LayerNorm: one block (128 thr) per output row -------------
// Rows j >= rows_in_per_b are the appended all-zero row: LN(0) = beta.
__global__ void ln_kernel(const float* __restrict__ x,
                          const float* __restrict__ gamma,
                          const float* __restrict__ beta,
                          float* __restrict__ y,
                          int rows_in_per_b, int rows_out_per_b) {
    int r = blockIdx.x;
    int b = r / rows_out_per_b;
    int j = r - b * rows_out_per_b;
    int t = threadIdx.x;  // 128 threads, 4 floats each

    float4 g4 = ((const float4*)gamma)[t];
    float4 b4 = ((const float4*)beta)[t];
    float4* yr = (float4*)(y + (size_t)r * DD);

    if (j >= rows_in_per_b) { yr[t] = b4; return; }

    const float4* xr = (const float4*)(x + ((size_t)b * rows_in_per_b + j) * DD);
    float4 v = xr[t];
    float s  = v.x + v.y + v.z + v.w;
    float sq = v.x*v.x + v.y*v.y + v.z*v.z + v.w*v.w;
    #pragma unroll
    for (int o = 16; o > 0; o >>= 1) {
        s  += __shfl_xor_sync(0xffffffffu, s,  o);
        sq += __shfl_xor_sync(0xffffffffu, sq, o);
    }
    __shared__ float rs[4], rq[4];
    int w = t >> 5;
    if ((t & 31) == 0) { rs[w] = s; rq[w] = sq; }
    __syncthreads();
    s  = rs[0] + rs[1] + rs[2] + rs[3];
    sq = rq[0] + rq[1] + rq[2] + rq[3];

    float mean = s * (1.0f / DD);
    float var  = sq * (1.0f / DD) - mean * mean;
    float rstd = rsqrtf(var + LN_EPS_F);

    float4 o;
    o.x = (v.x - mean) * rstd * g4.x + b4.x;
    o.y = (v.y - mean) * rstd * g4.y + b4.y;
    o.z = (v.z - mean) * rstd * g4.z + b4.z;
    o.w = (v.w - mean) * rstd * g4.w + b4.w;
    yr[t] = o;
}

// ---------------- fp32 GEMM: C[M,512] = A[M,512] @ W[512,512] ---------------
// BM=64 BN=64 BK=32, 256 threads, 4x4 micro-tile per thread.
__global__ void __launch_bounds__(256) gemm512(const float* __restrict__ A,
                                               const float* __restrict__ W,
                                               float* __restrict__ C, int M) {
    __shared__ float As[32][64];   // k-major: As[k][m]
    __shared__ float Ws[32][64];   // k-major: Ws[k][n]
    int tid = threadIdx.x;
    int tx = tid & 15, ty = tid >> 4;
    int m0 = blockIdx.y * 64;
    int n0 = blockIdx.x * 64;
    float acc[4][4] = {};

    for (int k0 = 0; k0 < 512; k0 += 32) {
        #pragma unroll
        for (int it = 0; it < 2; it++) {
            int f = tid + it * 256;          // 0..511 float4 slots
            int row = f >> 3;                // 8 float4 per 32-wide row
            int kc  = (f & 7) << 2;
            int gm  = m0 + row;
            float4 v = (gm < M) ? *(const float4*)(A + (size_t)gm * 512 + k0 + kc)
                                : make_float4(0.f, 0.f, 0.f, 0.f);
            As[kc + 0][row] = v.x; As[kc + 1][row] = v.y;
            As[kc + 2][row] = v.z; As[kc + 3][row] = v.w;
        }
        #pragma unroll
        for (int it = 0; it < 2; it++) {
            int f = tid + it * 256;
            int row = f >> 4;                // 16 float4 per 64-wide row
            int nc  = (f & 15) << 2;
            *(float4*)&Ws[row][nc] =
                *(const float4*)(W + (size_t)(k0 + row) * 512 + n0 + nc);
        }
        __syncthreads();
        #pragma unroll
        for (int k = 0; k < 32; k++) {
            float4 a = *(float4*)&As[k][ty * 4];
            float4 w = *(float4*)&Ws[k][tx * 4];
            float av[4] = {a.x, a.y, a.z, a.w};
            float wv[4] = {w.x, w.y, w.z, w.w};
            #pragma unroll
            for (int i = 0; i < 4; i++)
                #pragma unroll
                for (int j = 0; j < 4; j++)
                    acc[i][j] += av[i] * wv[j];
        }
        __syncthreads();
    }
    #pragma unroll
    for (int i = 0; i < 4; i++) {
        int gm = m0 + ty * 4 + i;
        if (gm < M) {
            float4 o = make_float4(acc[i][0], acc[i][1], acc[i][2], acc[i][3]);
            *(float4*)(C + (size_t)gm * 512 + n0 + tx * 4) = o;
        }
    }
}

// ---------------- flash attention: one CTA per (b, h, 64-query tile) --------
__global__ void __launch_bounds__(256) attn_kernel(const float* __restrict__ QHp,
                                                   const float* __restrict__ KHp,
                                                   const float* __restrict__ VHp,
                                                   const int* __restrict__ kmask,
                                                   const int* __restrict__ qmask,
                                                   float* __restrict__ AV) {
    __shared__ float Qs[64 * 64];    // Q^T: Qs[d*64 + q]
    __shared__ float KPs[64 * 64];   // K^T: KPs[d*64 + j], reused as P^T[j*64 + q]
    __shared__ float Vs[64 * 64];    // V  : Vs[j*64 + d]

    int tid = threadIdx.x;
    int tx = tid & 15, ty = tid >> 4;
    int qb = blockIdx.x * 64;
    int h  = blockIdx.y;
    int b  = blockIdx.z;
    size_t qrow0 = (size_t)b * QQ + qb;

    // Load Q tile transposed (once)
    #pragma unroll
    for (int it = 0; it < 4; it++) {
        int f = tid + it * 256;          // 0..1023 float4
        int q = f >> 4;                  // 16 float4 per 64-d row
        int d = (f & 15) << 2;
        float4 v = *(const float4*)(QHp + (qrow0 + q) * DD + h * HD + d);
        Qs[(d + 0) * 64 + q] = v.x; Qs[(d + 1) * 64 + q] = v.y;
        Qs[(d + 2) * 64 + q] = v.z; Qs[(d + 3) * 64 + q] = v.w;
    }

    float mrow[4], lrow[4], O[4][4];
    #pragma unroll
    for (int i = 0; i < 4; i++) {
        mrow[i] = NEG_INF_F; lrow[i] = 0.f;
        #pragma unroll
        for (int j = 0; j < 4; j++) O[i][j] = 0.f;
    }

    for (int t0 = 0; t0 < KP; t0 += 64) {
        __syncthreads();   // previous P.V GEMM finished reading KPs/Vs
        #pragma unroll
        for (int it = 0; it < 4; it++) {
            int f = tid + it * 256;
            int j = f >> 4;
            int d = (f & 15) << 2;
            int jg = t0 + j;
            float4 kv = make_float4(0.f, 0.f, 0.f, 0.f);
            float4 vv = make_float4(0.f, 0.f, 0.f, 0.f);
            if (jg < KP) {
                size_t roff = ((size_t)b * KP + jg) * DD + h * HD + d;
                kv = *(const float4*)(KHp + roff);
                vv = *(const float4*)(VHp + roff);
            }
            KPs[(d + 0) * 64 + j] = kv.x; KPs[(d + 1) * 64 + j] = kv.y;
            KPs[(d + 2) * 64 + j] = kv.z; KPs[(d + 3) * 64 + j] = kv.w;
            *(float4*)&Vs[j * 64 + d] = vv;
        }
        __syncthreads();

        // S = Q K^T (4x4 per thread)
        float s[4][4] = {};
        #pragma unroll
        for (int d = 0; d < 64; d++) {
            float4 a = *(float4*)&Qs[d * 64 + ty * 4];
            float4 k = *(float4*)&KPs[d * 64 + tx * 4];
            float av[4] = {a.x, a.y, a.z, a.w};
            float kv[4] = {k.x, k.y, k.z, k.w};
            #pragma unroll
            for (int i = 0; i < 4; i++)
                #pragma unroll
                for (int j = 0; j < 4; j++)
                    s[i][j] += av[i] * kv[j];
        }

        // scale + key mask (appended slot j==KLEN is always valid)
        bool valid[4];
        #pragma unroll
        for (int j = 0; j < 4; j++) {
            int jg = t0 + tx * 4 + j;
            valid[j] = (jg < KP) && ((jg == KLEN) || (kmask[b * KLEN + jg] != 0));
        }
        #pragma unroll
        for (int i = 0; i < 4; i++)
            #pragma unroll
            for (int j = 0; j < 4; j++)
                s[i][j] = valid[j] ? s[i][j] * SCALE_F : NEG_INF_F;

        // online softmax (row reduce across tx via shfl, lanes 0..15 per ty)
        #pragma unroll
        for (int i = 0; i < 4; i++) {
            float mx = fmaxf(fmaxf(s[i][0], s[i][1]), fmaxf(s[i][2], s[i][3]));
            #pragma unroll
            for (int o = 8; o > 0; o >>= 1)
                mx = fmaxf(mx, __shfl_xor_sync(0xffffffffu, mx, o));
            float mn = fmaxf(mrow[i], mx);
            float alpha = __expf(mrow[i] - mn);
            float rsum = 0.f;
            #pragma unroll
            for (int j = 0; j < 4; j++) {
                float p = __expf(s[i][j] - mn);
                s[i][j] = p;
                rsum += p;
            }
            #pragma unroll
            for (int o = 8; o > 0; o >>= 1)
                rsum += __shfl_xor_sync(0xffffffffu, rsum, o);
            lrow[i] = lrow[i] * alpha + rsum;
            #pragma unroll
            for (int j = 0; j < 4; j++) O[i][j] *= alpha;
            mrow[i] = mn;
        }

        __syncthreads();   // done reading KPs as K^T
        // store P^T into KPs: P^T[j][q]
        #pragma unroll
        for (int i = 0; i < 4; i++)
            #pragma unroll
            for (int j = 0; j < 4; j++)
                KPs[(tx * 4 + j) * 64 + ty * 4 + i] = s[i][j];
        __syncthreads();

        // O += P V
        #pragma unroll
        for (int jj = 0; jj < 64; jj++) {
            float4 p = *(float4*)&KPs[jj * 64 + ty * 4];
            float4 v = *(float4*)&Vs[jj * 64 + tx * 4];
            float pv[4] = {p.x, p.y, p.z, p.w};
            float vv[4] = {v.x, v.y, v.z, v.w};
            #pragma unroll
            for (int i = 0; i < 4; i++)
                #pragma unroll
                for (int j = 0; j < 4; j++)
                    O[i][j] += pv[i] * vv[j];
        }
    }

    // epilogue: normalize, apply query mask, write AV
    #pragma unroll
    for (int i = 0; i < 4; i++) {
        int qg = qb + ty * 4 + i;
        float qm = (qmask[b * QQ + qg] != 0) ? 1.0f : 0.0f;
        float inv = qm / lrow[i];
        float4 o = make_float4(O[i][0] * inv, O[i][1] * inv,
                               O[i][2] * inv, O[i][3] * inv);
        *(float4*)(AV + (qrow0 + ty * 4 + i) * DD + h * HD + tx * 4) = o;
    }
}

// ---------------- g_net GEMM (K=1024 over [query | AVO]) + gated residual ---
__global__ void __launch_bounds__(256) gnet_gemm(const float* __restrict__ Aq,
                                                 const float* __restrict__ Av,
                                                 const float* __restrict__ GW,
                                                 const float* __restrict__ gb,
                                                 float* __restrict__ out) {
    __shared__ float As[32][64];
    __shared__ float Ws[32][64];
    int tid = threadIdx.x;
    int tx = tid & 15, ty = tid >> 4;
    int m0 = blockIdx.y * 64;
    int n0 = blockIdx.x * 64;
    float acc[4][4] = {};

    for (int k0 = 0; k0 < 1024; k0 += 32) {
        const float* A = (k0 < 512) ? Aq : Av;
        int kk = k0 & 511;
        #pragma unroll
        for (int it = 0; it < 2; it++) {
            int f = tid + it * 256;
            int row = f >> 3;
            int kc  = (f & 7) << 2;
            float4 v = *(const float4*)(A + (size_t)(m0 + row) * 512 + kk + kc);
            As[kc + 0][row] = v.x; As[kc + 1][row] = v.y;
            As[kc + 2][row] = v.z; As[kc + 3][row] = v.w;
        }
        #pragma unroll
        for (int it = 0; it < 2; it++) {
            int f = tid + it * 256;
            int row = f >> 4;
            int nc  = (f & 15) << 2;
            *(float4*)&Ws[row][nc] =
                *(const float4*)(GW + (size_t)(k0 + row) * 512 + n0 + nc);
        }
        __syncthreads();
        #pragma unroll
        for (int k = 0; k < 32; k++) {
            float4 a = *(float4*)&As[k][ty * 4];
            float4 w = *(float4*)&Ws[k][tx * 4];
            float av[4] = {a.x, a.y, a.z, a.w};
            float wv[4] = {w.x, w.y, w.z, w.w};
            #pragma unroll
            for (int i = 0; i < 4; i++)
                #pragma unroll
                for (int j = 0; j < 4; j++)
                    acc[i][j] += av[i] * wv[j];
        }
        __syncthreads();
    }

    float4 bb = *(const float4*)(gb + n0 + tx * 4);
    float bv[4] = {bb.x, bb.y, bb.z, bb.w};
    #pragma unroll
    for (int i = 0; i < 4; i++) {
        size_t gm = m0 + ty * 4 + i;
        float4 qv4 = *(const float4*)(Aq + gm * 512 + n0 + tx * 4);
        float4 av4 = *(const float4*)(Av + gm * 512 + n0 + tx * 4);
        float qv[4] = {qv4.x, qv4.y, qv4.z, qv4.w};
        float av[4] = {av4.x, av4.y, av4.z, av4.w};
        float o[4];
        #pragma unroll
        for (int j = 0; j < 4; j++) {
            float g = 1.0f / (1.0f + __expf(-(acc[i][j] + bv[j])));
            // out = q + g*q + (1-g)*av
            o[j] = qv[j] + g * qv[j] + (1.0f - g) * av[j];
        }
        *(float4*)(out + gm * 512 + n0 + tx * 4) =
            make_float4(o[0], o[1], o[2], o[3]);
    }
}

// ---------------- launch ----------------------------------------------------
extern "C" void kernel_launch(void* const* d_in, const int* in_sizes, int n_in,
                              void* d_out, int out_size) {
    const float* query = (const float*)d_in[0];
    const float* key   = (const float*)d_in[1];
    const float* value = (const float*)d_in[2];
    const float* wq    = (const float*)d_in[3];
    const float* wk    = (const float*)d_in[4];
    const float* wv    = (const float*)d_in[5];
    const float* wo    = (const float*)d_in[6];
    const float* gw    = (const float*)d_in[7];
    const float* gb    = (const float*)d_in[8];
    const float* qg    = (const float*)d_in[9];
    const float* qbv   = (const float*)d_in[10];
    const float* kg    = (const float*)d_in[11];
    const float* kbv   = (const float*)d_in[12];
    const float* vg    = (const float*)d_in[13];
    const float* vbv   = (const float*)d_in[14];
    const int* qmask   = (const int*)d_in[15];
    const int* kmask   = (const int*)d_in[16];
    float* out = (float*)d_out;

    float *QN, *KN, *VN, *QH, *KH, *VH, *AV, *AVO;
    cudaGetSymbolAddress((void**)&QN,  g_QN);
    cudaGetSymbolAddress((void**)&KN,  g_KN);
    cudaGetSymbolAddress((void**)&VN,  g_VN);
    cudaGetSymbolAddress((void**)&QH,  g_QH);
    cudaGetSymbolAddress((void**)&KH,  g_KH);
    cudaGetSymbolAddress((void**)&VH,  g_VH);
    cudaGetSymbolAddress((void**)&AV,  g_AV);
    cudaGetSymbolAddress((void**)&AVO, g_AVO);

    // 1) pre-layernorm (zero-append handled in-kernel: LN(0) = beta)
    ln_kernel<<<BB * QQ, 128>>>(query, qg, qbv, QN, QQ, QQ);
    ln_kernel<<<BB * KP, 128>>>(key,   kg, kbv, KN, KLEN, KP);
    ln_kernel<<<BB * KP, 128>>>(value, vg, vbv, VN, KLEN, KP);

    // 2) projections
    gemm512<<<dim3(8, 64), 256>>>(QN, wq, QH, BB * QQ);
    gemm512<<<dim3(8, 65), 256>>>(KN, wk, KH, BB * KP);
    gemm512<<<dim3(8, 65), 256>>>(VN, wv, VH, BB * KP);

    // 3) flash attention (writes query-masked attn_vec into AV)
    attn_kernel<<<dim3(QQ / 64, NH, BB), 256>>>(QH, KH, VH, kmask, qmask, AV);

    // 4) output projection
    gemm512<<<dim3(8, 64), 256>>>(AV, wo, AVO, BB * QQ);

    // 5) g_net + gated combination + residual -> d_out
    gnet_gemm<<<dim3(8, 64), 256>>>(query, AVO, gw, gb, out);
}

// round 3
// speedup vs baseline: 1.5512x; 1.5512x over previous
#include <cuda_runtime.h>
#include <math.h>

#define BB   2
#define QQ   2048
#define KLEN 2048
#define KP   2049
#define DD   512
#define NH   8
#define HD   64
#define SCALE_F   0.125f
#define NEG_INF_F -1e30f
#define LN_EPS_F  1e-5f

typedef unsigned long long ull;

// ---------------- packed f32x2 helpers --------------------------------------
__device__ __forceinline__ ull dup2(float x) {
    ull r; asm("mov.b64 %0, {%1, %1};" : "=l"(r) : "f"(x)); return r;
}
__device__ __forceinline__ ull pack2(float lo, float hi) {
    ull r; asm("mov.b64 %0, {%1, %2};" : "=l"(r) : "f"(lo), "f"(hi)); return r;
}
__device__ __forceinline__ void fma2(ull& d, ull a, ull b) {
    asm("fma.rn.f32x2 %0, %1, %2, %0;" : "+l"(d) : "l"(a), "l"(b));
}
__device__ __forceinline__ void mul2(ull& d, ull a) {
    asm("mul.rn.f32x2 %0, %0, %1;" : "+l"(d) : "l"(a));
}
__device__ __forceinline__ float lo2(ull v) { return ((float2*)&v)->x; }
__device__ __forceinline__ float hi2(ull v) { return ((float2*)&v)->y; }

// ---------------- scratch ----------------------------------------------------
__device__ float g_QN[BB * QQ * DD];
__device__ float g_KN[BB * KP * DD];
__device__ float g_VN[BB * KP * DD];
__device__ float g_QH[BB * QQ * DD];
__device__ float g_KH[BB * KP * DD];
__device__ float g_VH[BB * KP * DD];
__device__ float g_AV[BB * QQ * DD];
__device__ float g_AVO[BB * QQ * DD];

// ---------------- LayerNorm --------------------------------------------------
__global__ void ln_kernel(const float* __restrict__ x,
                          const float* __restrict__ gamma,
                          const float* __restrict__ beta,
                          float* __restrict__ y,
                          int rows_in_per_b, int rows_out_per_b) {
    int r = blockIdx.x;
    int b = r / rows_out_per_b;
    int j = r - b * rows_out_per_b;
    int t = threadIdx.x;

    float4 g4 = ((const float4*)gamma)[t];
    float4 b4 = ((const float4*)beta)[t];
    float4* yr = (float4*)(y + (size_t)r * DD);

    if (j >= rows_in_per_b) { yr[t] = b4; return; }

    const float4* xr = (const float4*)(x + ((size_t)b * rows_in_per_b + j) * DD);
    float4 v = xr[t];
    float s  = v.x + v.y + v.z + v.w;
    float sq = v.x*v.x + v.y*v.y + v.z*v.z + v.w*v.w;
    #pragma unroll
    for (int o = 16; o > 0; o >>= 1) {
        s  += __shfl_xor_sync(0xffffffffu, s,  o);
        sq += __shfl_xor_sync(0xffffffffu, sq, o);
    }
    __shared__ float rs[4], rq[4];
    int w = t >> 5;
    if ((t & 31) == 0) { rs[w] = s; rq[w] = sq; }
    __syncthreads();
    s  = rs[0] + rs[1] + rs[2] + rs[3];
    sq = rq[0] + rq[1] + rq[2] + rq[3];

    float mean = s * (1.0f / DD);
    float var  = sq * (1.0f / DD) - mean * mean;
    float rstd = rsqrtf(var + LN_EPS_F);

    float4 o;
    o.x = (v.x - mean) * rstd * g4.x + b4.x;
    o.y = (v.y - mean) * rstd * g4.y + b4.y;
    o.z = (v.z - mean) * rstd * g4.z + b4.z;
    o.w = (v.w - mean) * rstd * g4.w + b4.w;
    yr[t] = o;
}

// ---------------- GEMM v2: C[M,512] = A[M,512] @ W[512,512] ------------------
// BM=128 BN=64 BK=16, 256 threads, 8x4 micro-tile, f32x2, double-buffered.
__global__ void __launch_bounds__(256) gemm512_v2(const float* __restrict__ A,
                                                  const float* __restrict__ W,
                                                  float* __restrict__ C, int M) {
    __shared__ float As[2][16 * 128];
    __shared__ float Ws[2][16 * 64];
    int tid = threadIdx.x;
    int tx = tid & 15, ty = tid >> 4;
    int m0 = blockIdx.y * 128;
    int n0 = blockIdx.x * 64;

    ull acc[4][4];
    #pragma unroll
    for (int i = 0; i < 4; i++)
        #pragma unroll
        for (int j = 0; j < 4; j++) acc[i][j] = 0ull;

    // staging regs
    float4 ra0, ra1, rw;
    int am0 = tid >> 2, ac0 = (tid & 3);          // A: f=tid
    int am1 = (tid + 256) >> 2, ac1 = (tid & 3);  // A: f=tid+256
    int wk = tid >> 4, wn = tid & 15;             // W: one float4/thread

    // LDG for k-tile kt
    auto ldgA = [&](int kt) {
        int k0 = kt * 16;
        int r0 = m0 + am0; if (r0 > M - 1) r0 = M - 1;
        int r1 = m0 + am1; if (r1 > M - 1) r1 = M - 1;
        ra0 = *(const float4*)(A + (size_t)r0 * 512 + k0 + ac0 * 4);
        ra1 = *(const float4*)(A + (size_t)r1 * 512 + k0 + ac1 * 4);
        rw  = *(const float4*)(W + (size_t)(k0 + wk) * 512 + n0 + wn * 4);
    };
    auto sts = [&](int buf) {
        // A: transpose-store with 16B-chunk XOR swizzle, key = row>>2 = kc
        float va[2][4] = {{ra0.x, ra0.y, ra0.z, ra0.w}, {ra1.x, ra1.y, ra1.z, ra1.w}};
        int mm[2] = {am0, am1};
        #pragma unroll
        for (int p = 0; p < 2; p++) {
            int m = mm[p], kc = (p == 0) ? ac0 : ac1;
            #pragma unroll
            for (int i = 0; i < 4; i++) {
                int row = 4 * kc + i;
                As[buf][row * 128 + (((m >> 2) ^ kc) << 2) + (m & 3)] = va[p][i];
            }
        }
        *(float4*)&Ws[buf][wk * 64 + ((wn ^ (wk >> 2)) << 2)] = rw;
    };

    ldgA(0); sts(0); __syncthreads();

    for (int kt = 0; kt < 32; kt++) {
        int cur = kt & 1;
        if (kt < 31) ldgA(kt + 1);
        #pragma unroll
        for (int k = 0; k < 16; k++) {
            int key = k >> 2;
            float4 aa = *(float4*)&As[cur][k * 128 + (((2 * ty    ) ^ key) << 2)];
            float4 ab = *(float4*)&As[cur][k * 128 + (((2 * ty + 1) ^ key) << 2)];
            float4 wf = *(float4*)&Ws[cur][k * 64 + ((tx ^ key) << 2)];
            ull a0 = pack2(aa.x, aa.y), a1 = pack2(aa.z, aa.w);
            ull a2 = pack2(ab.x, ab.y), a3 = pack2(ab.z, ab.w);
            ull w0 = dup2(wf.x), w1 = dup2(wf.y), w2 = dup2(wf.z), w3 = dup2(wf.w);
            fma2(acc[0][0], a0, w0); fma2(acc[0][1], a0, w1);
            fma2(acc[0][2], a0, w2); fma2(acc[0][3], a0, w3);
            fma2(acc[1][0], a1, w0); fma2(acc[1][1], a1, w1);
            fma2(acc[1][2], a1, w2); fma2(acc[1][3], a1, w3);
            fma2(acc[2][0], a2, w0); fma2(acc[2][1], a2, w1);
            fma2(acc[2][2], a2, w2); fma2(acc[2][3], a2, w3);
            fma2(acc[3][0], a3, w0); fma2(acc[3][1], a3, w1);
            fma2(acc[3][2], a3, w2); fma2(acc[3][3], a3, w3);
        }
        if (kt < 31) sts(1 - cur);
        __syncthreads();
    }

    #pragma unroll
    for (int i2 = 0; i2 < 4; i2++) {
        #pragma unroll
        for (int sel = 0; sel < 2; sel++) {
            int m = m0 + ty * 8 + 2 * i2 + sel;
            if (m < M) {
                float4 o;
                o.x = sel ? hi2(acc[i2][0]) : lo2(acc[i2][0]);
                o.y = sel ? hi2(acc[i2][1]) : lo2(acc[i2][1]);
                o.z = sel ? hi2(acc[i2][2]) : lo2(acc[i2][2]);
                o.w = sel ? hi2(acc[i2][3]) : lo2(acc[i2][3]);
                *(float4*)(C + (size_t)m * 512 + n0 + tx * 4) = o;
            }
        }
    }
}

// ---------------- flash attention v2: 128q x 64k, f32x2, swizzled smem -------
__global__ void __launch_bounds__(256, 2) attn_kernel(const float* __restrict__ QHp,
                                                      const float* __restrict__ KHp,
                                                      const float* __restrict__ VHp,
                                                      const int* __restrict__ kmask,
                                                      const int* __restrict__ qmask,
                                                      float* __restrict__ AV) {
    extern __shared__ float sm[];
    float* QT = sm;              // 64 x 128  (d-major, swizzled)  32KB
    float* KT = QT + 64 * 128;   // 64 x 64   (d-major, swizzled)  16KB
    float* Vs = KT + 64 * 64;    // 64 x 64   (j-major, linear)    16KB
    float* PT = Vs + 64 * 64;    // 64 x 128  (j-major, swizzled)  32KB

    int tid = threadIdx.x;
    int tx = tid & 15, ty = tid >> 4;
    int qb = blockIdx.x * 128;
    int h  = blockIdx.y;
    int b  = blockIdx.z;
    size_t qrow0 = (size_t)b * QQ + qb;

    // ---- load Q tile transposed+swizzled, pre-scaled by SCALE ----
    #pragma unroll
    for (int it = 0; it < 8; it++) {
        int f = tid + it * 256;         // 0..2047
        int q = f >> 4;                 // 0..127
        int dc = f & 15;                // float4 within d
        float4 v = *(const float4*)(QHp + (qrow0 + q) * DD + h * HD + dc * 4);
        v.x *= SCALE_F; v.y *= SCALE_F; v.z *= SCALE_F; v.w *= SCALE_F;
        float vv[4] = {v.x, v.y, v.z, v.w};
        #pragma unroll
        for (int i = 0; i < 4; i++) {
            int row = 4 * dc + i;       // d
            QT[row * 128 + (((q >> 2) ^ dc) << 2) + (q & 3)] = vv[i];
        }
    }

    float mrow[8], lrow[8];
    ull O2[4][4];
    #pragma unroll
    for (int r = 0; r < 8; r++) { mrow[r] = NEG_INF_F; lrow[r] = 0.f; }
    #pragma unroll
    for (int i = 0; i < 4; i++)
        #pragma unroll
        for (int j = 0; j < 4; j++) O2[i][j] = 0ull;

    for (int t0 = 0; t0 < KP; t0 += 64) {
        __syncthreads();
        // ---- load K (transposed+swizzled) and V (linear) ----
        #pragma unroll
        for (int it = 0; it < 4; it++) {
            int f = tid + it * 256;     // 0..1023
            int j = f >> 4;             // 0..63
            int dc = f & 15;
            int jg = t0 + j;
            float4 kv = make_float4(0.f, 0.f, 0.f, 0.f);
            float4 vv = make_float4(0.f, 0.f, 0.f, 0.f);
            if (jg < KP) {
                size_t roff = ((size_t)b * KP + jg) * DD + h * HD + dc * 4;
                kv = *(const float4*)(KHp + roff);
                vv = *(const float4*)(VHp + roff);
            }
            float ka[4] = {kv.x, kv.y, kv.z, kv.w};
            #pragma unroll
            for (int i = 0; i < 4; i++) {
                int row = 4 * dc + i;   // d
                KT[row * 64 + (((j >> 2) ^ dc) << 2) + (j & 3)] = ka[i];
            }
            *(float4*)&Vs[j * 64 + dc * 4] = vv;
        }
        __syncthreads();

        // ---- S = Q K^T ----
        ull s2[4][4];
        #pragma unroll
        for (int i = 0; i < 4; i++)
            #pragma unroll
            for (int j = 0; j < 4; j++) s2[i][j] = 0ull;

        #pragma unroll 8
        for (int d = 0; d < 64; d++) {
            int key = d >> 2;
            float4 qa = *(float4*)&QT[d * 128 + (((2 * ty    ) ^ key) << 2)];
            float4 qb4= *(float4*)&QT[d * 128 + (((2 * ty + 1) ^ key) << 2)];
            float4 kf = *(float4*)&KT[d * 64 + ((tx ^ key) << 2)];
            ull a0 = pack2(qa.x, qa.y),  a1 = pack2(qa.z, qa.w);
            ull a2 = pack2(qb4.x, qb4.y), a3 = pack2(qb4.z, qb4.w);
            ull k0 = dup2(kf.x), k1 = dup2(kf.y), k2 = dup2(kf.z), k3 = dup2(kf.w);
            fma2(s2[0][0], a0, k0); fma2(s2[0][1], a0, k1);
            fma2(s2[0][2], a0, k2); fma2(s2[0][3], a0, k3);
            fma2(s2[1][0], a1, k0); fma2(s2[1][1], a1, k1);
            fma2(s2[1][2], a1, k2); fma2(s2[1][3], a1, k3);
            fma2(s2[2][0], a2, k0); fma2(s2[2][1], a2, k1);
            fma2(s2[2][2], a2, k2); fma2(s2[2][3], a2, k3);
            fma2(s2[3][0], a3, k0); fma2(s2[3][1], a3, k1);
            fma2(s2[3][2], a3, k2); fma2(s2[3][3], a3, k3);
        }

        // ---- key mask (add -inf to invalid columns) ----
        float nm[4];
        #pragma unroll
        for (int j = 0; j < 4; j++) {
            int jg = t0 + tx * 4 + j;
            bool valid;
            if (jg < KLEN)      valid = (kmask[b * KLEN + jg] != 0);
            else if (jg == KLEN) valid = true;
            else                 valid = false;
            nm[j] = valid ? 0.0f : NEG_INF_F;
        }
        #pragma unroll
        for (int i2 = 0; i2 < 4; i2++)
            #pragma unroll
            for (int j = 0; j < 4; j++) {
                float2 t = *(float2*)&s2[i2][j];
                t.x += nm[j]; t.y += nm[j];
                *(float2*)&s2[i2][j] = t;
            }

        // ---- online softmax (rows) ----
        float af[8];
        #pragma unroll
        for (int r = 0; r < 8; r++) {
            int i2 = r >> 1;
            float sv[4];
            #pragma unroll
            for (int j = 0; j < 4; j++) {
                float2 t = *(float2*)&s2[i2][j];
                sv[j] = (r & 1) ? t.y : t.x;
            }
            float mx = fmaxf(fmaxf(sv[0], sv[1]), fmaxf(sv[2], sv[3]));
            #pragma unroll
            for (int o = 8; o > 0; o >>= 1)
                mx = fmaxf(mx, __shfl_xor_sync(0xffffffffu, mx, o));
            float mn = fmaxf(mrow[r], mx);
            float al = __expf(mrow[r] - mn);
            float rs = 0.f;
            #pragma unroll
            for (int j = 0; j < 4; j++) { sv[j] = __expf(sv[j] - mn); rs += sv[j]; }
            #pragma unroll
            for (int o = 8; o > 0; o >>= 1)
                rs += __shfl_xor_sync(0xffffffffu, rs, o);
            lrow[r] = lrow[r] * al + rs;
            mrow[r] = mn;
            af[r] = al;
            #pragma unroll
            for (int j = 0; j < 4; j++) {
                float2 t = *(float2*)&s2[i2][j];
                if (r & 1) t.y = sv[j]; else t.x = sv[j];
                *(float2*)&s2[i2][j] = t;
            }
        }
        // rescale O
        #pragma unroll
        for (int i2 = 0; i2 < 4; i2++) {
            ull ap = pack2(af[2 * i2], af[2 * i2 + 1]);
            #pragma unroll
            for (int j = 0; j < 4; j++) mul2(O2[i2][j], ap);
        }

        // ---- store P^T (swizzled) ----
        #pragma unroll
        for (int j = 0; j < 4; j++) {
            int row = tx * 4 + j;       // key index within tile
            float2 p0 = *(float2*)&s2[0][j];
            float2 p1 = *(float2*)&s2[1][j];
            float2 p2 = *(float2*)&s2[2][j];
            float2 p3 = *(float2*)&s2[3][j];
            float4 lo = make_float4(p0.x, p0.y, p1.x, p1.y);
            float4 hi = make_float4(p2.x, p2.y, p3.x, p3.y);
            int key = row >> 2;         // == tx
            *(float4*)&PT[row * 128 + (((2 * ty    ) ^ key) << 2)] = lo;
            *(float4*)&PT[row * 128 + (((2 * ty + 1) ^ key) << 2)] = hi;
        }
        __syncthreads();

        // ---- O += P V ----
        #pragma unroll 8
        for (int jj = 0; jj < 64; jj++) {
            int key = jj >> 2;
            float4 pa = *(float4*)&PT[jj * 128 + (((2 * ty    ) ^ key) << 2)];
            float4 pb = *(float4*)&PT[jj * 128 + (((2 * ty + 1) ^ key) << 2)];
            float4 vf = *(float4*)&Vs[jj * 64 + tx * 4];
            ull p0 = pack2(pa.x, pa.y), p1 = pack2(pa.z, pa.w);
            ull p2 = pack2(pb.x, pb.y), p3 = pack2(pb.z, pb.w);
            ull v0 = dup2(vf.x), v1 = dup2(vf.y), v2 = dup2(vf.z), v3 = dup2(vf.w);
            fma2(O2[0][0], p0, v0); fma2(O2[0][1], p0, v1);
            fma2(O2[0][2], p0, v2); fma2(O2[0][3], p0, v3);
            fma2(O2[1][0], p1, v0); fma2(O2[1][1], p1, v1);
            fma2(O2[1][2], p1, v2); fma2(O2[1][3], p1, v3);
            fma2(O2[2][0], p2, v0); fma2(O2[2][1], p2, v1);
            fma2(O2[2][2], p2, v2); fma2(O2[2][3], p2, v3);
            fma2(O2[3][0], p3, v0); fma2(O2[3][1], p3, v1);
            fma2(O2[3][2], p3, v2); fma2(O2[3][3], p3, v3);
        }
    }

    // ---- epilogue ----
    #pragma unroll
    for (int r = 0; r < 8; r++) {
        int qg = qb + ty * 8 + r;
        float qm = (qmask[b * QQ + qg] != 0) ? 1.0f : 0.0f;
        float inv = qm / lrow[r];
        int i2 = r >> 1;
        float4 o;
        float2 t0_ = *(float2*)&O2[i2][0];
        float2 t1_ = *(float2*)&O2[i2][1];
        float2 t2_ = *(float2*)&O2[i2][2];
        float2 t3_ = *(float2*)&O2[i2][3];
        o.x = ((r & 1) ? t0_.y : t0_.x) * inv;
        o.y = ((r & 1) ? t1_.y : t1_.x) * inv;
        o.z = ((r & 1) ? t2_.y : t2_.x) * inv;
        o.w = ((r & 1) ? t3_.y : t3_.x) * inv;
        *(float4*)(AV + (qrow0 + ty * 8 + r) * DD + h * HD + tx * 4) = o;
    }
}

// ---------------- g_net GEMM (K=1024) + gated residual -----------------------
__global__ void __launch_bounds__(256) gnet_gemm_v2(const float* __restrict__ Aq,
                                                    const float* __restrict__ Av,
                                                    const float* __restrict__ GW,
                                                    const float* __restrict__ gb,
                                                    float* __restrict__ out) {
    __shared__ float As[2][16 * 128];
    __shared__ float Ws[2][16 * 64];
    int tid = threadIdx.x;
    int tx = tid & 15, ty = tid >> 4;
    int m0 = blockIdx.y * 128;
    int n0 = blockIdx.x * 64;

    ull acc[4][4];
    #pragma unroll
    for (int i = 0; i < 4; i++)
        #pragma unroll
        for (int j = 0; j < 4; j++) acc[i][j] = 0ull;

    float4 ra0, ra1, rw;
    int am0 = tid >> 2, ac0 = (tid & 3);
    int am1 = (tid + 256) >> 2, ac1 = (tid & 3);
    int wk = tid >> 4, wn = tid & 15;

    auto ldg = [&](int kt) {
        int k0 = kt * 16;
        const float* A = (k0 < 512) ? Aq : Av;
        int kk = k0 & 511;
        ra0 = *(const float4*)(A + (size_t)(m0 + am0) * 512 + kk + ac0 * 4);
        ra1 = *(const float4*)(A + (size_t)(m0 + am1) * 512 + kk + ac1 * 4);
        rw  = *(const float4*)(GW + (size_t)(k0 + wk) * 512 + n0 + wn * 4);
    };
    auto sts = [&](int buf) {
        float va[2][4] = {{ra0.x, ra0.y, ra0.z, ra0.w}, {ra1.x, ra1.y, ra1.z, ra1.w}};
        int mm[2] = {am0, am1};
        #pragma unroll
        for (int p = 0; p < 2; p++) {
            int m = mm[p], kc = (p == 0) ? ac0 : ac1;
            #pragma unroll
            for (int i = 0; i < 4; i++) {
                int row = 4 * kc + i;
                As[buf][row * 128 + (((m >> 2) ^ kc) << 2) + (m & 3)] = va[p][i];
            }
        }
        *(float4*)&Ws[buf][wk * 64 + ((wn ^ (wk >> 2)) << 2)] = rw;
    };

    ldg(0); sts(0); __syncthreads();

    for (int kt = 0; kt < 64; kt++) {
        int cur = kt & 1;
        if (kt < 63) ldg(kt + 1);
        #pragma unroll
        for (int k = 0; k < 16; k++) {
            int key = k >> 2;
            float4 aa = *(float4*)&As[cur][k * 128 + (((2 * ty    ) ^ key) << 2)];
            float4 ab = *(float4*)&As[cur][k * 128 + (((2 * ty + 1) ^ key) << 2)];
            float4 wf = *(float4*)&Ws[cur][k * 64 + ((tx ^ key) << 2)];
            ull a0 = pack2(aa.x, aa.y), a1 = pack2(aa.z, aa.w);
            ull a2 = pack2(ab.x, ab.y), a3 = pack2(ab.z, ab.w);
            ull w0 = dup2(wf.x), w1 = dup2(wf.y), w2 = dup2(wf.z), w3 = dup2(wf.w);
            fma2(acc[0][0], a0, w0); fma2(acc[0][1], a0, w1);
            fma2(acc[0][2], a0, w2); fma2(acc[0][3], a0, w3);
            fma2(acc[1][0], a1, w0); fma2(acc[1][1], a1, w1);
            fma2(acc[1][2], a1, w2); fma2(acc[1][3], a1, w3);
            fma2(acc[2][0], a2, w0); fma2(acc[2][1], a2, w1);
            fma2(acc[2][2], a2, w2); fma2(acc[2][3], a2, w3);
            fma2(acc[3][0], a3, w0); fma2(acc[3][1], a3, w1);
            fma2(acc[3][2], a3, w2); fma2(acc[3][3], a3, w3);
        }
        if (kt < 63) sts(1 - cur);
        __syncthreads();
    }

    float4 bb = *(const float4*)(gb + n0 + tx * 4);
    float bv[4] = {bb.x, bb.y, bb.z, bb.w};
    #pragma unroll
    for (int i2 = 0; i2 < 4; i2++) {
        #pragma unroll
        for (int sel = 0; sel < 2; sel++) {
            size_t m = m0 + ty * 8 + 2 * i2 + sel;
            float4 qv4 = *(const float4*)(Aq + m * 512 + n0 + tx * 4);
            float4 av4 = *(const float4*)(Av + m * 512 + n0 + tx * 4);
            float qv[4] = {qv4.x, qv4.y, qv4.z, qv4.w};
            float av[4] = {av4.x, av4.y, av4.z, av4.w};
            float sc[4];
            sc[0] = sel ? hi2(acc[i2][0]) : lo2(acc[i2][0]);
            sc[1] = sel ? hi2(acc[i2][1]) : lo2(acc[i2][1]);
            sc[2] = sel ? hi2(acc[i2][2]) : lo2(acc[i2][2]);
            sc[3] = sel ? hi2(acc[i2][3]) : lo2(acc[i2][3]);
            float o[4];
            #pragma unroll
            for (int j = 0; j < 4; j++) {
                float g = 1.0f / (1.0f + __expf(-(sc[j] + bv[j])));
                o[j] = qv[j] + g * qv[j] + (1.0f - g) * av[j];
            }
            *(float4*)(out + m * 512 + n0 + tx * 4) = make_float4(o[0], o[1], o[2], o[3]);
        }
    }
}

// ---------------- launch ------------------------------------------------------
extern "C" void kernel_launch(void* const* d_in, const int* in_sizes, int n_in,
                              void* d_out, int out_size) {
    const float* query = (const float*)d_in[0];
    const float* key   = (const float*)d_in[1];
    const float* value = (const float*)d_in[2];
    const float* wq    = (const float*)d_in[3];
    const float* wk    = (const float*)d_in[4];
    const float* wv    = (const float*)d_in[5];
    const float* wo    = (const float*)d_in[6];
    const float* gw    = (const float*)d_in[7];
    const float* gb    = (const float*)d_in[8];
    const float* qg    = (const float*)d_in[9];
    const float* qbv   = (const float*)d_in[10];
    const float* kg    = (const float*)d_in[11];
    const float* kbv   = (const float*)d_in[12];
    const float* vg    = (const float*)d_in[13];
    const float* vbv   = (const float*)d_in[14];
    const int* qmask   = (const int*)d_in[15];
    const int* kmask   = (const int*)d_in[16];
    float* out = (float*)d_out;

    float *QN, *KN, *VN, *QH, *KH, *VH, *AV, *AVO;
    cudaGetSymbolAddress((void**)&QN,  g_QN);
    cudaGetSymbolAddress((void**)&KN,  g_KN);
    cudaGetSymbolAddress((void**)&VN,  g_VN);
    cudaGetSymbolAddress((void**)&QH,  g_QH);
    cudaGetSymbolAddress((void**)&KH,  g_KH);
    cudaGetSymbolAddress((void**)&VH,  g_VH);
    cudaGetSymbolAddress((void**)&AV,  g_AV);
    cudaGetSymbolAddress((void**)&AVO, g_AVO);

    static const int ATT_SMEM = 96 * 1024;
    cudaFuncSetAttribute(attn_kernel, cudaFuncAttributeMaxDynamicSharedMemorySize, ATT_SMEM);

    // 1) pre-layernorm
    ln_kernel<<<BB * QQ, 128>>>(query, qg, qbv, QN, QQ, QQ);
    ln_kernel<<<BB * KP, 128>>>(key,   kg, kbv, KN, KLEN, KP);
    ln_kernel<<<BB * KP, 128>>>(value, vg, vbv, VN, KLEN, KP);

    // 2) projections
    gemm512_v2<<<dim3(8, 32), 256>>>(QN, wq, QH, BB * QQ);
    gemm512_v2<<<dim3(8, 33), 256>>>(KN, wk, KH, BB * KP);
    gemm512_v2<<<dim3(8, 33), 256>>>(VN, wv, VH, BB * KP);

    // 3) flash attention
    attn_kernel<<<dim3(QQ / 128, NH, BB), 256, ATT_SMEM>>>(QH, KH, VH, kmask, qmask, AV);

    // 4) output projection
    gemm512_v2<<<dim3(8, 32), 256>>>(AV, wo, AVO, BB * QQ);

    // 5) g_net + gate + residual
    gnet_gemm_v2<<<dim3(8, 32), 256>>>(query, AVO, gw, gb, out);
}

// round 5
// speedup vs baseline: 2.7034x; 1.7428x over previous
#include <cuda_runtime.h>
#include <math.h>
#include <stdint.h>

#define BB   2
#define QQ   2048
#define KLEN 2048
#define KP   2049
#define DD   512
#define NH   8
#define HD   64
#define SCALE_F   0.125f
#define NEG_INF_F -1e30f
#define LN_EPS_F  1e-5f

// ---------------- tf32 mma helpers -------------------------------------------
__device__ __forceinline__ uint32_t f2tf(float f) {
    uint32_t u; asm("cvt.rna.tf32.f32 %0, %1;" : "=r"(u) : "f"(f)); return u;
}
__device__ __forceinline__ void mma8(float c[4], uint32_t a0, uint32_t a1,
                                     uint32_t a2, uint32_t a3,
                                     uint32_t b0, uint32_t b1) {
    asm volatile("mma.sync.aligned.m16n8k8.row.col.f32.tf32.tf32.f32 "
        "{%0,%1,%2,%3}, {%4,%5,%6,%7}, {%8,%9}, {%0,%1,%2,%3};"
        : "+f"(c[0]), "+f"(c[1]), "+f"(c[2]), "+f"(c[3])
        : "r"(a0), "r"(a1), "r"(a2), "r"(a3), "r"(b0), "r"(b1));
}

// fragment k-permutation within a k8 group: p = ((kk&3)<<1)|(kk>>2)
#define KPERM(kk) ((((kk) & 3) << 1) | ((kk) >> 2))

// ---------------- scratch ----------------------------------------------------
__device__ float g_QN[BB * QQ * DD];
__device__ float g_KN[BB * KP * DD];
__device__ float g_VN[BB * KP * DD];
__device__ float g_QH[BB * QQ * DD];
__device__ float g_KH[BB * KP * DD];
__device__ float g_VH[BB * KP * DD];
__device__ float g_AV[BB * QQ * DD];
__device__ float g_AVO[BB * QQ * DD];
__device__ float g_WTq[DD * DD];
__device__ float g_WTk[DD * DD];
__device__ float g_WTv[DD * DD];
__device__ float g_WTo[DD * DD];
__device__ float g_GWT[DD * 2 * DD];

// ---------------- transpose: WT[n][k] = W[k][n] -------------------------------
__global__ void transpose_kn(const float* __restrict__ W, float* __restrict__ WT,
                             int K, int N) {
    __shared__ float t[32][33];
    int kx = blockIdx.x * 32, ny = blockIdx.y * 32;
    int x = threadIdx.x, y = threadIdx.y;   // block (32, 8)
    #pragma unroll
    for (int i = 0; i < 32; i += 8)
        t[y + i][x] = W[(size_t)(kx + y + i) * N + ny + x];
    __syncthreads();
    #pragma unroll
    for (int i = 0; i < 32; i += 8)
        WT[(size_t)(ny + y + i) * K + kx + x] = t[x][y + i];
}

// ---------------- LayerNorm --------------------------------------------------
__global__ void ln_kernel(const float* __restrict__ x,
                          const float* __restrict__ gamma,
                          const float* __restrict__ beta,
                          float* __restrict__ y,
                          int rows_in_per_b, int rows_out_per_b) {
    int r = blockIdx.x;
    int b = r / rows_out_per_b;
    int j = r - b * rows_out_per_b;
    int t = threadIdx.x;

    float4 g4 = ((const float4*)gamma)[t];
    float4 b4 = ((const float4*)beta)[t];
    float4* yr = (float4*)(y + (size_t)r * DD);

    if (j >= rows_in_per_b) { yr[t] = b4; return; }

    const float4* xr = (const float4*)(x + ((size_t)b * rows_in_per_b + j) * DD);
    float4 v = xr[t];
    float s  = v.x + v.y + v.z + v.w;
    float sq = v.x*v.x + v.y*v.y + v.z*v.z + v.w*v.w;
    #pragma unroll
    for (int o = 16; o > 0; o >>= 1) {
        s  += __shfl_xor_sync(0xffffffffu, s,  o);
        sq += __shfl_xor_sync(0xffffffffu, sq, o);
    }
    __shared__ float rs[4], rq[4];
    int w = t >> 5;
    if ((t & 31) == 0) { rs[w] = s; rq[w] = sq; }
    __syncthreads();
    s  = rs[0] + rs[1] + rs[2] + rs[3];
    sq = rq[0] + rq[1] + rq[2] + rq[3];

    float mean = s * (1.0f / DD);
    float var  = sq * (1.0f / DD) - mean * mean;
    float rstd = rsqrtf(var + LN_EPS_F);

    float4 o;
    o.x = (v.x - mean) * rstd * g4.x + b4.x;
    o.y = (v.y - mean) * rstd * g4.y + b4.y;
    o.z = (v.z - mean) * rstd * g4.z + b4.z;
    o.w = (v.w - mean) * rstd * g4.w + b4.w;
    yr[t] = o;
}

// ---------------- tf32 warp-MMA GEMM -----------------------------------------
// C[M,512] = A[M,512] @ Bt[512,512]^T (Bt n-major). BM=BN=128, BK=32.
// 256 thr = 8 warps (2m x 4n), warp tile 64x32.
#define SA 36
#define GEMM_SMEM (4 * 128 * SA * 4)

extern __shared__ float smf[];

__global__ void __launch_bounds__(256) mm_proj(const float* __restrict__ A,
                                               const float* __restrict__ Bt,
                                               float* __restrict__ C, int M) {
    float* As0 = smf;
    float* As1 = smf + 128 * SA;
    float* Bs0 = smf + 2 * 128 * SA;
    float* Bs1 = smf + 3 * 128 * SA;
    int tid = threadIdx.x;
    int lane = tid & 31, wid = tid >> 5;
    int g = lane >> 2, t4 = lane & 3;
    int mw = wid & 1, nw = wid >> 1;
    int n0 = blockIdx.x * 128, m0 = blockIdx.y * 128;

    float acc[4][4][4] = {};
    float4 ra[4], rb[4];

    auto ldg = [&](int kt) {
        int k0 = kt * 32;
        #pragma unroll
        for (int it = 0; it < 4; it++) {
            int f = tid + it * 256; int r = f >> 3; int c4 = f & 7;
            int gm = m0 + r; if (gm > M - 1) gm = M - 1;
            ra[it] = *(const float4*)(A  + (size_t)gm * 512 + k0 + c4 * 4);
            rb[it] = *(const float4*)(Bt + (size_t)(n0 + r) * 512 + k0 + c4 * 4);
        }
    };
    auto sts = [&](float* Ab, float* Bb) {
        #pragma unroll
        for (int it = 0; it < 4; it++) {
            int f = tid + it * 256; int r = f >> 3; int c4 = f & 7;
            float va[4] = {ra[it].x, ra[it].y, ra[it].z, ra[it].w};
            float vb[4] = {rb[it].x, rb[it].y, rb[it].z, rb[it].w};
            #pragma unroll
            for (int i = 0; i < 4; i++) {
                int k = c4 * 4 + i; int kg = k >> 3, kk = k & 7;
                int p = KPERM(kk);
                ((uint32_t*)Ab)[r * SA + kg * 8 + p] = f2tf(va[i]);
                ((uint32_t*)Bb)[r * SA + kg * 8 + p] = f2tf(vb[i]);
            }
        }
    };
    auto compute = [&](float* Ab, float* Bb) {
        #pragma unroll
        for (int kg = 0; kg < 4; kg++) {
            uint2 a02[4], a13[4];
            #pragma unroll
            for (int mi = 0; mi < 4; mi++) {
                int r = mw * 64 + mi * 16 + g;
                a02[mi] = *(uint2*)((uint32_t*)Ab + r * SA + kg * 8 + 2 * t4);
                a13[mi] = *(uint2*)((uint32_t*)Ab + (r + 8) * SA + kg * 8 + 2 * t4);
            }
            #pragma unroll
            for (int ni = 0; ni < 4; ni++) {
                int nr = nw * 32 + ni * 8 + g;
                uint2 bf = *(uint2*)((uint32_t*)Bb + nr * SA + kg * 8 + 2 * t4);
                #pragma unroll
                for (int mi = 0; mi < 4; mi++)
                    mma8(acc[mi][ni], a02[mi].x, a13[mi].x, a02[mi].y, a13[mi].y,
                         bf.x, bf.y);
            }
        }
    };

    ldg(0); sts(As0, Bs0); __syncthreads();
    const int T = 16;
    for (int t = 0; t < T; t++) {
        if (t + 1 < T) ldg(t + 1);
        if (t & 1) compute(As1, Bs1); else compute(As0, Bs0);
        if (t + 1 < T) { if (t & 1) sts(As0, Bs0); else sts(As1, Bs1); }
        __syncthreads();
    }

    #pragma unroll
    for (int mi = 0; mi < 4; mi++) {
        int r0 = m0 + mw * 64 + mi * 16 + g;
        #pragma unroll
        for (int ni = 0; ni < 4; ni++) {
            int c = n0 + nw * 32 + ni * 8 + 2 * t4;
            if (r0 < M)
                *(float2*)(C + (size_t)r0 * 512 + c) =
                    make_float2(acc[mi][ni][0], acc[mi][ni][1]);
            if (r0 + 8 < M)
                *(float2*)(C + (size_t)(r0 + 8) * 512 + c) =
                    make_float2(acc[mi][ni][2], acc[mi][ni][3]);
        }
    }
}

// ---------------- tf32 warp-MMA g_net GEMM (K=1024) + gated residual ---------
__global__ void __launch_bounds__(256) mm_gnet(const float* __restrict__ Aq,
                                               const float* __restrict__ Av,
                                               const float* __restrict__ GWT,
                                               const float* __restrict__ gbv,
                                               float* __restrict__ out) {
    float* As0 = smf;
    float* As1 = smf + 128 * SA;
    float* Bs0 = smf + 2 * 128 * SA;
    float* Bs1 = smf + 3 * 128 * SA;
    int tid = threadIdx.x;
    int lane = tid & 31, wid = tid >> 5;
    int g = lane >> 2, t4 = lane & 3;
    int mw = wid & 1, nw = wid >> 1;
    int n0 = blockIdx.x * 128, m0 = blockIdx.y * 128;

    float acc[4][4][4] = {};
    float4 ra[4], rb[4];

    auto ldg = [&](int kt) {
        const float* Ap = (kt < 16) ? Aq : Av;
        int ka = (kt & 15) * 32;
        int kb = kt * 32;
        #pragma unroll
        for (int it = 0; it < 4; it++) {
            int f = tid + it * 256; int r = f >> 3; int c4 = f & 7;
            ra[it] = *(const float4*)(Ap + (size_t)(m0 + r) * 512 + ka + c4 * 4);
            rb[it] = *(const float4*)(GWT + (size_t)(n0 + r) * 1024 + kb + c4 * 4);
        }
    };
    auto sts = [&](float* Ab, float* Bb) {
        #pragma unroll
        for (int it = 0; it < 4; it++) {
            int f = tid + it * 256; int r = f >> 3; int c4 = f & 7;
            float va[4] = {ra[it].x, ra[it].y, ra[it].z, ra[it].w};
            float vb[4] = {rb[it].x, rb[it].y, rb[it].z, rb[it].w};
            #pragma unroll
            for (int i = 0; i < 4; i++) {
                int k = c4 * 4 + i; int kg = k >> 3, kk = k & 7;
                int p = KPERM(kk);
                ((uint32_t*)Ab)[r * SA + kg * 8 + p] = f2tf(va[i]);
                ((uint32_t*)Bb)[r * SA + kg * 8 + p] = f2tf(vb[i]);
            }
        }
    };
    auto compute = [&](float* Ab, float* Bb) {
        #pragma unroll
        for (int kg = 0; kg < 4; kg++) {
            uint2 a02[4], a13[4];
            #pragma unroll
            for (int mi = 0; mi < 4; mi++) {
                int r = mw * 64 + mi * 16 + g;
                a02[mi] = *(uint2*)((uint32_t*)Ab + r * SA + kg * 8 + 2 * t4);
                a13[mi] = *(uint2*)((uint32_t*)Ab + (r + 8) * SA + kg * 8 + 2 * t4);
            }
            #pragma unroll
            for (int ni = 0; ni < 4; ni++) {
                int nr = nw * 32 + ni * 8 + g;
                uint2 bf = *(uint2*)((uint32_t*)Bb + nr * SA + kg * 8 + 2 * t4);
                #pragma unroll
                for (int mi = 0; mi < 4; mi++)
                    mma8(acc[mi][ni], a02[mi].x, a13[mi].x, a02[mi].y, a13[mi].y,
                         bf.x, bf.y);
            }
        }
    };

    ldg(0); sts(As0, Bs0); __syncthreads();
    const int T = 32;
    for (int t = 0; t < T; t++) {
        if (t + 1 < T) ldg(t + 1);
        if (t & 1) compute(As1, Bs1); else compute(As0, Bs0);
        if (t + 1 < T) { if (t & 1) sts(As0, Bs0); else sts(As1, Bs1); }
        __syncthreads();
    }

    #pragma unroll
    for (int mi = 0; mi < 4; mi++) {
        int r0 = m0 + mw * 64 + mi * 16 + g;
        #pragma unroll
        for (int ni = 0; ni < 4; ni++) {
            int c = n0 + nw * 32 + ni * 8 + 2 * t4;
            float2 bb = *(const float2*)(gbv + c);
            #pragma unroll
            for (int sel = 0; sel < 2; sel++) {
                size_t r = r0 + sel * 8;
                float2 qv = *(const float2*)(Aq + r * 512 + c);
                float2 av = *(const float2*)(Av + r * 512 + c);
                float s0 = acc[mi][ni][sel * 2 + 0] + bb.x;
                float s1 = acc[mi][ni][sel * 2 + 1] + bb.y;
                float g0 = 1.0f / (1.0f + __expf(-s0));
                float g1 = 1.0f / (1.0f + __expf(-s1));
                float o0 = qv.x + g0 * qv.x + (1.0f - g0) * av.x;
                float o1 = qv.y + g1 * qv.y + (1.0f - g1) * av.y;
                *(float2*)(out + r * 512 + c) = make_float2(o0, o1);
            }
        }
    }
}

// ---------------- flash attention with tf32 warp-MMA -------------------------
// 128q x 64k tiles, 8 warps x 16 q-rows each; fragment-permuted SMEM.
#define SQ 68
#define ATT_SMEM ((128 * SQ + 64 * SQ + 64 * SQ + 128 * SQ + 64) * 4)

__global__ void __launch_bounds__(256) attn_kernel(const float* __restrict__ QHp,
                                                   const float* __restrict__ KHp,
                                                   const float* __restrict__ VHp,
                                                   const int* __restrict__ kmask,
                                                   const int* __restrict__ qmask,
                                                   float* __restrict__ AV) {
    float* Qs = smf;                 // [128][SQ] tf32, fragment-permuted
    float* Ks = Qs + 128 * SQ;       // [64][SQ]  (n=key rows)
    float* Vs = Ks + 64 * SQ;        // [64][SQ]  (n=d rows, k=key permuted)
    float* Ps = Vs + 64 * SQ;        // [128][SQ] (A-frag layout for PV)
    float* Ms = Ps + 128 * SQ;       // [64] mask add values

    int tid = threadIdx.x;
    int lane = tid & 31, wid = tid >> 5;
    int g = lane >> 2, t4 = lane & 3;
    int qw = wid * 16;
    int qb = blockIdx.x * 128, h = blockIdx.y, b = blockIdx.z;
    size_t qrow0 = (size_t)b * QQ + qb;

    // stage Q (pre-scaled, tf32, permuted)
    #pragma unroll
    for (int it = 0; it < 8; it++) {
        int f = tid + it * 256; int q = f >> 4; int c4 = f & 15;
        float4 v = *(const float4*)(QHp + (qrow0 + q) * 512 + h * 64 + c4 * 4);
        float va[4] = {v.x * SCALE_F, v.y * SCALE_F, v.z * SCALE_F, v.w * SCALE_F};
        #pragma unroll
        for (int i = 0; i < 4; i++) {
            int d = c4 * 4 + i; int kg = d >> 3, kk = d & 7;
            ((uint32_t*)Qs)[q * SQ + kg * 8 + KPERM(kk)] = f2tf(va[i]);
        }
    }

    float mr[2] = {NEG_INF_F, NEG_INF_F};   // rows qw+g, qw+g+8
    float lr[2] = {0.f, 0.f};
    float O[8][4] = {};

    for (int t0 = 0; t0 < KP; t0 += 64) {
        __syncthreads();   // prev iter done reading Ks/Vs/Ms
        // stage K (permuted), V (transposed+permuted), mask
        #pragma unroll
        for (int it = 0; it < 4; it++) {
            int f = tid + it * 256; int j = f >> 4; int c4 = f & 15;
            int jg = t0 + j;
            float4 kv = make_float4(0.f, 0.f, 0.f, 0.f);
            float4 vv = make_float4(0.f, 0.f, 0.f, 0.f);
            if (jg < KP) {
                size_t ro = ((size_t)b * KP + jg) * 512 + h * 64 + c4 * 4;
                kv = *(const float4*)(KHp + ro);
                vv = *(const float4*)(VHp + ro);
            }
            float ka[4] = {kv.x, kv.y, kv.z, kv.w};
            float va[4] = {vv.x, vv.y, vv.z, vv.w};
            int jcol = (j >> 3) * 8 + KPERM(j & 7);
            #pragma unroll
            for (int i = 0; i < 4; i++) {
                int d = c4 * 4 + i; int kg = d >> 3, kk = d & 7;
                ((uint32_t*)Ks)[j * SQ + kg * 8 + KPERM(kk)] = f2tf(ka[i]);
                ((uint32_t*)Vs)[d * SQ + jcol] = f2tf(va[i]);
            }
        }
        if (tid < 64) {
            int jg = t0 + tid;
            bool valid = (jg < KLEN) ? (kmask[b * KLEN + jg] != 0) : (jg == KLEN);
            Ms[tid] = valid ? 0.0f : NEG_INF_F;
        }
        __syncthreads();

        // ---- S = Q K^T ----
        float s[8][4] = {};
        #pragma unroll
        for (int kg = 0; kg < 8; kg++) {
            uint2 a02 = *(uint2*)((uint32_t*)Qs + (qw + g) * SQ + kg * 8 + 2 * t4);
            uint2 a13 = *(uint2*)((uint32_t*)Qs + (qw + g + 8) * SQ + kg * 8 + 2 * t4);
            #pragma unroll
            for (int ni = 0; ni < 8; ni++) {
                uint2 bf = *(uint2*)((uint32_t*)Ks + (ni * 8 + g) * SQ + kg * 8 + 2 * t4);
                mma8(s[ni], a02.x, a13.x, a02.y, a13.y, bf.x, bf.y);
            }
        }
        // mask
        #pragma unroll
        for (int ni = 0; ni < 8; ni++) {
            float2 mk = *(float2*)&Ms[ni * 8 + 2 * t4];
            s[ni][0] += mk.x; s[ni][1] += mk.y;
            s[ni][2] += mk.x; s[ni][3] += mk.y;
        }
        // ---- online softmax (row0: regs 0,1; row1: regs 2,3) ----
        float mx0 = NEG_INF_F, mx1 = NEG_INF_F;
        #pragma unroll
        for (int ni = 0; ni < 8; ni++) {
            mx0 = fmaxf(mx0, fmaxf(s[ni][0], s[ni][1]));
            mx1 = fmaxf(mx1, fmaxf(s[ni][2], s[ni][3]));
        }
        mx0 = fmaxf(mx0, __shfl_xor_sync(0xffffffffu, mx0, 1));
        mx0 = fmaxf(mx0, __shfl_xor_sync(0xffffffffu, mx0, 2));
        mx1 = fmaxf(mx1, __shfl_xor_sync(0xffffffffu, mx1, 1));
        mx1 = fmaxf(mx1, __shfl_xor_sync(0xffffffffu, mx1, 2));
        float mn0 = fmaxf(mr[0], mx0), mn1 = fmaxf(mr[1], mx1);
        float al0 = __expf(mr[0] - mn0), al1 = __expf(mr[1] - mn1);
        float sum0 = 0.f, sum1 = 0.f;
        #pragma unroll
        for (int ni = 0; ni < 8; ni++) {
            s[ni][0] = __expf(s[ni][0] - mn0); sum0 += s[ni][0];
            s[ni][1] = __expf(s[ni][1] - mn0); sum0 += s[ni][1];
            s[ni][2] = __expf(s[ni][2] - mn1); sum1 += s[ni][2];
            s[ni][3] = __expf(s[ni][3] - mn1); sum1 += s[ni][3];
        }
        sum0 += __shfl_xor_sync(0xffffffffu, sum0, 1);
        sum0 += __shfl_xor_sync(0xffffffffu, sum0, 2);
        sum1 += __shfl_xor_sync(0xffffffffu, sum1, 1);
        sum1 += __shfl_xor_sync(0xffffffffu, sum1, 2);
        lr[0] = lr[0] * al0 + sum0;
        lr[1] = lr[1] * al1 + sum1;
        mr[0] = mn0; mr[1] = mn1;
        #pragma unroll
        for (int ni = 0; ni < 8; ni++) {
            O[ni][0] *= al0; O[ni][1] *= al0;
            O[ni][2] *= al1; O[ni][3] *= al1;
        }
        // ---- store P in A-fragment layout (warp-private rows) ----
        {
            int kk0 = 2 * t4, kk1 = 2 * t4 + 1;
            int p0 = KPERM(kk0), p1 = KPERM(kk1);
            #pragma unroll
            for (int ni = 0; ni < 8; ni++) {
                ((uint32_t*)Ps)[(qw + g) * SQ + ni * 8 + p0]     = f2tf(s[ni][0]);
                ((uint32_t*)Ps)[(qw + g) * SQ + ni * 8 + p1]     = f2tf(s[ni][1]);
                ((uint32_t*)Ps)[(qw + g + 8) * SQ + ni * 8 + p0] = f2tf(s[ni][2]);
                ((uint32_t*)Ps)[(qw + g + 8) * SQ + ni * 8 + p1] = f2tf(s[ni][3]);
            }
        }
        __syncwarp();

        // ---- O += P V ----
        #pragma unroll
        for (int kg = 0; kg < 8; kg++) {
            uint2 a02 = *(uint2*)((uint32_t*)Ps + (qw + g) * SQ + kg * 8 + 2 * t4);
            uint2 a13 = *(uint2*)((uint32_t*)Ps + (qw + g + 8) * SQ + kg * 8 + 2 * t4);
            #pragma unroll
            for (int ni = 0; ni < 8; ni++) {
                uint2 bf = *(uint2*)((uint32_t*)Vs + (ni * 8 + g) * SQ + kg * 8 + 2 * t4);
                mma8(O[ni], a02.x, a13.x, a02.y, a13.y, bf.x, bf.y);
            }
        }
    }

    // ---- epilogue: normalize, query mask, write ----
    int r0 = qb + qw + g, r1 = r0 + 8;
    float qm0 = (qmask[b * QQ + r0] != 0) ? 1.0f : 0.0f;
    float qm1 = (qmask[b * QQ + r1] != 0) ? 1.0f : 0.0f;
    float inv0 = qm0 / lr[0], inv1 = qm1 / lr[1];
    #pragma unroll
    for (int ni = 0; ni < 8; ni++) {
        int c = h * 64 + ni * 8 + 2 * t4;
        *(float2*)(AV + (qrow0 + qw + g) * 512 + c) =
            make_float2(O[ni][0] * inv0, O[ni][1] * inv0);
        *(float2*)(AV + (qrow0 + qw + g + 8) * 512 + c) =
            make_float2(O[ni][2] * inv1, O[ni][3] * inv1);
    }
}

// ---------------- launch ------------------------------------------------------
extern "C" void kernel_launch(void* const* d_in, const int* in_sizes, int n_in,
                              void* d_out, int out_size) {
    const float* query = (const float*)d_in[0];
    const float* key   = (const float*)d_in[1];
    const float* value = (const float*)d_in[2];
    const float* wq    = (const float*)d_in[3];
    const float* wk    = (const float*)d_in[4];
    const float* wv    = (const float*)d_in[5];
    const float* wo    = (const float*)d_in[6];
    const float* gw    = (const float*)d_in[7];
    const float* gb    = (const float*)d_in[8];
    const float* qg    = (const float*)d_in[9];
    const float* qbv   = (const float*)d_in[10];
    const float* kg    = (const float*)d_in[11];
    const float* kbv   = (const float*)d_in[12];
    const float* vg    = (const float*)d_in[13];
    const float* vbv   = (const float*)d_in[14];
    const int* qmask   = (const int*)d_in[15];
    const int* kmask   = (const int*)d_in[16];
    float* out = (float*)d_out;

    float *QN, *KN, *VN, *QH, *KH, *VH, *AV, *AVO;
    float *WTq, *WTk, *WTv, *WTo, *GWT;
    cudaGetSymbolAddress((void**)&QN,  g_QN);
    cudaGetSymbolAddress((void**)&KN,  g_KN);
    cudaGetSymbolAddress((void**)&VN,  g_VN);
    cudaGetSymbolAddress((void**)&QH,  g_QH);
    cudaGetSymbolAddress((void**)&KH,  g_KH);
    cudaGetSymbolAddress((void**)&VH,  g_VH);
    cudaGetSymbolAddress((void**)&AV,  g_AV);
    cudaGetSymbolAddress((void**)&AVO, g_AVO);
    cudaGetSymbolAddress((void**)&WTq, g_WTq);
    cudaGetSymbolAddress((void**)&WTk, g_WTk);
    cudaGetSymbolAddress((void**)&WTv, g_WTv);
    cudaGetSymbolAddress((void**)&WTo, g_WTo);
    cudaGetSymbolAddress((void**)&GWT, g_GWT);

    cudaFuncSetAttribute(attn_kernel, cudaFuncAttributeMaxDynamicSharedMemorySize, ATT_SMEM);
    cudaFuncSetAttribute(mm_proj, cudaFuncAttributeMaxDynamicSharedMemorySize, GEMM_SMEM);
    cudaFuncSetAttribute(mm_gnet, cudaFuncAttributeMaxDynamicSharedMemorySize, GEMM_SMEM);

    // 0) weight transposes (WT[n][k] = W[k][n])
    transpose_kn<<<dim3(16, 16), dim3(32, 8)>>>(wq, WTq, 512, 512);
    transpose_kn<<<dim3(16, 16), dim3(32, 8)>>>(wk, WTk, 512, 512);
    transpose_kn<<<dim3(16, 16), dim3(32, 8)>>>(wv, WTv, 512, 512);
    transpose_kn<<<dim3(16, 16), dim3(32, 8)>>>(wo, WTo, 512, 512);
    transpose_kn<<<dim3(32, 16), dim3(32, 8)>>>(gw, GWT, 1024, 512);

    // 1) pre-layernorm
    ln_kernel<<<BB * QQ, 128>>>(query, qg, qbv, QN, QQ, QQ);
    ln_kernel<<<BB * KP, 128>>>(key,   kg, kbv, KN, KLEN, KP);
    ln_kernel<<<BB * KP, 128>>>(value, vg, vbv, VN, KLEN, KP);

    // 2) projections (tf32 warp MMA)
    mm_proj<<<dim3(4, 32), 256, GEMM_SMEM>>>(QN, WTq, QH, BB * QQ);
    mm_proj<<<dim3(4, 33), 256, GEMM_SMEM>>>(KN, WTk, KH, BB * KP);
    mm_proj<<<dim3(4, 33), 256, GEMM_SMEM>>>(VN, WTv, VH, BB * KP);

    // 3) flash attention (tf32 warp MMA)
    attn_kernel<<<dim3(QQ / 128, NH, BB), 256, ATT_SMEM>>>(QH, KH, VH, kmask, qmask, AV);

    // 4) output projection
    mm_proj<<<dim3(4, 32), 256, GEMM_SMEM>>>(AV, WTo, AVO, BB * QQ);

    // 5) g_net + gate + residual
    mm_gnet<<<dim3(4, 32), 256, GEMM_SMEM>>>(query, AVO, GWT, gb, out);
}